// round 2
// baseline (speedup 1.0000x reference)
#include <cuda_runtime.h>
#include <math.h>

#define N_NODES 50000
#define N_EDGES 800000
#define ET      (N_EDGES + N_NODES)   // 850000 incl. self-loops
#define DIN     256
#define HEADS   8
#define CH      32
#define DOUT    256
#define CAP     128                   // max in-degree bucket (Poisson(16): overflow prob ~0)
#define NEG_SLOPE 0.2f
#define LN_EPS  1e-5f

// ---------------- static device scratch (no allocations allowed) ----------------
__device__ float g_h[(size_t)N_NODES * DOUT];       // 51.2 MB, fits L2
__device__ float g_asrc[N_NODES * HEADS];
__device__ float g_adst[N_NODES * HEADS];
__device__ int   g_cnt[N_NODES];
__device__ int   g_csr_src[(size_t)N_NODES * CAP];  // 25.6 MB

// ---------------- kernel 0: clear bucket counters ----------------
__global__ void zero_kernel() {
    int t = blockIdx.x * blockDim.x + threadIdx.x;
    if (t < N_NODES) g_cnt[t] = 0;
}

// ---------------- kernel 1: h = x @ W  (fp32 tiled GEMM) ----------------
#define BM 128
#define BN 64
#define BK 16
#define TM 8
#define TN 4

__global__ __launch_bounds__(256) void gemm_kernel(const float* __restrict__ A,
                                                   const float* __restrict__ B) {
    __shared__ float As[BK][BM + 4];   // +4 pad: break STS bank conflicts, keep 16B align
    __shared__ float Bs[BK][BN];

    int tid = threadIdx.x;
    int ty = tid >> 4;        // 0..15
    int tx = tid & 15;        // 0..15
    int m0 = blockIdx.x * BM;
    int n0 = blockIdx.y * BN;

    float acc[TM][TN];
#pragma unroll
    for (int i = 0; i < TM; i++)
#pragma unroll
        for (int j = 0; j < TN; j++) acc[i][j] = 0.f;

    int arow  = tid >> 2;          // 0..63
    int acol4 = (tid & 3) * 4;     // 0,4,8,12
    int brow  = tid >> 4;          // 0..15
    int bcol4 = (tid & 15) * 4;    // 0..60

    for (int k0 = 0; k0 < DIN; k0 += BK) {
#pragma unroll
        for (int r = 0; r < 2; r++) {
            int m = m0 + arow + r * 64;
            float4 v = make_float4(0.f, 0.f, 0.f, 0.f);
            if (m < N_NODES) v = *(const float4*)(A + (size_t)m * DIN + k0 + acol4);
            As[acol4 + 0][arow + r * 64] = v.x;
            As[acol4 + 1][arow + r * 64] = v.y;
            As[acol4 + 2][arow + r * 64] = v.z;
            As[acol4 + 3][arow + r * 64] = v.w;
        }
        {
            float4 v = *(const float4*)(B + (size_t)(k0 + brow) * DOUT + n0 + bcol4);
            *(float4*)&Bs[brow][bcol4] = v;
        }
        __syncthreads();
#pragma unroll
        for (int k = 0; k < BK; k++) {
            float a[TM], b[TN];
            const float4* ap = (const float4*)&As[k][ty * TM];
            float4 a0 = ap[0], a1 = ap[1];
            a[0]=a0.x; a[1]=a0.y; a[2]=a0.z; a[3]=a0.w;
            a[4]=a1.x; a[5]=a1.y; a[6]=a1.z; a[7]=a1.w;
            float4 b0 = *(const float4*)&Bs[k][tx * TN];
            b[0]=b0.x; b[1]=b0.y; b[2]=b0.z; b[3]=b0.w;
#pragma unroll
            for (int i = 0; i < TM; i++)
#pragma unroll
                for (int j = 0; j < TN; j++)
                    acc[i][j] += a[i] * b[j];
        }
        __syncthreads();
    }
#pragma unroll
    for (int i = 0; i < TM; i++) {
        int m = m0 + ty * TM + i;
        if (m < N_NODES) {
            float4 v = make_float4(acc[i][0], acc[i][1], acc[i][2], acc[i][3]);
            *(float4*)(g_h + (size_t)m * DOUT + n0 + tx * TN) = v;
        }
    }
}

// ---------------- kernel 2: per-node attention dots ----------------
__global__ void node_attn_kernel(const float* __restrict__ att_src,
                                 const float* __restrict__ att_dst) {
    int warp  = (blockIdx.x * blockDim.x + threadIdx.x) >> 5;
    int lane  = threadIdx.x & 31;
    int nwarp = (gridDim.x * blockDim.x) >> 5;
    for (int n = warp; n < N_NODES; n += nwarp) {
        const float* hr = g_h + (size_t)n * DOUT;
#pragma unroll
        for (int j = 0; j < HEADS; j++) {
            float v  = hr[j * CH + lane];
            float ps = v * att_src[j * CH + lane];
            float pd = v * att_dst[j * CH + lane];
#pragma unroll
            for (int o = 16; o > 0; o >>= 1) {
                ps += __shfl_xor_sync(0xFFFFFFFFu, ps, o);
                pd += __shfl_xor_sync(0xFFFFFFFFu, pd, o);
            }
            if (lane == 0) {
                g_asrc[n * HEADS + j] = ps;
                g_adst[n * HEADS + j] = pd;
            }
        }
    }
}

// ---------------- kernel 3: bucket edges by dst (edge_index is int32!) ----------------
__global__ void scatter_kernel(const int* __restrict__ ei) {
    int t = blockIdx.x * blockDim.x + threadIdx.x;
    if (t >= ET) return;
    int s, d;
    if (t < N_EDGES) {
        s = ei[t];
        d = ei[N_EDGES + t];
    } else {
        s = d = t - N_EDGES;      // self-loop
    }
    if ((unsigned)s >= N_NODES || (unsigned)d >= N_NODES) return;  // safety clamp
    int pos = atomicAdd(&g_cnt[d], 1);
    if (pos < CAP) g_csr_src[(size_t)d * CAP + pos] = s;
}

// ---------------- kernel 4: warp-per-dst softmax-aggregate + bias + LN + ReLU ----------------
__global__ __launch_bounds__(256) void aggr_kernel(const float* __restrict__ bias,
                                                   const float* __restrict__ gamma,
                                                   const float* __restrict__ beta,
                                                   float* __restrict__ out) {
    int warp = (blockIdx.x * blockDim.x + threadIdx.x) >> 5;
    int lane = threadIdx.x & 31;
    if (warp >= N_NODES) return;
    int d    = warp;
    int head = lane >> 2;            // lane owns elements [lane*8, lane*8+8) -> single head
    int base = lane * 8;

    float adv = g_adst[d * HEADS + head];
    int cnt = g_cnt[d];
    if (cnt > CAP) cnt = CAP;

    float4 acc0 = make_float4(0.f, 0.f, 0.f, 0.f);
    float4 acc1 = make_float4(0.f, 0.f, 0.f, 0.f);
    float  S = 0.f;

    const int* lst = g_csr_src + (size_t)d * CAP;
    int s = (cnt > 0) ? lst[0] : 0;
    for (int i = 0; i < cnt; i++) {
        int s_nxt = (i + 1 < cnt) ? lst[i + 1] : 0;   // break pointer-chase chain
        float e = g_asrc[s * HEADS + head] + adv;
        e = (e > 0.f) ? e : NEG_SLOPE * e;
        float ex = __expf(e);                          // max-subtraction cancels in ratio
        S += ex;
        const float4* hp = (const float4*)(g_h + (size_t)s * DOUT + base);
        float4 h0 = hp[0], h1 = hp[1];
        acc0.x += ex * h0.x; acc0.y += ex * h0.y; acc0.z += ex * h0.z; acc0.w += ex * h0.w;
        acc1.x += ex * h1.x; acc1.y += ex * h1.y; acc1.z += ex * h1.z; acc1.w += ex * h1.w;
        s = s_nxt;
    }
    float inv = 1.f / S;

    float v[8];
    v[0] = acc0.x * inv + bias[base + 0];
    v[1] = acc0.y * inv + bias[base + 1];
    v[2] = acc0.z * inv + bias[base + 2];
    v[3] = acc0.w * inv + bias[base + 3];
    v[4] = acc1.x * inv + bias[base + 4];
    v[5] = acc1.y * inv + bias[base + 5];
    v[6] = acc1.z * inv + bias[base + 6];
    v[7] = acc1.w * inv + bias[base + 7];

    // LayerNorm over the 256-wide row held across the warp
    float sum = 0.f, sq = 0.f;
#pragma unroll
    for (int k = 0; k < 8; k++) { sum += v[k]; sq += v[k] * v[k]; }
#pragma unroll
    for (int o = 16; o > 0; o >>= 1) {
        sum += __shfl_xor_sync(0xFFFFFFFFu, sum, o);
        sq  += __shfl_xor_sync(0xFFFFFFFFu, sq,  o);
    }
    float mu   = sum * (1.f / 256.f);
    float var  = sq * (1.f / 256.f) - mu * mu;
    float rstd = rsqrtf(var + LN_EPS);

    float r[8];
#pragma unroll
    for (int k = 0; k < 8; k++) {
        float t = (v[k] - mu) * rstd * gamma[base + k] + beta[base + k];
        r[k] = (t > 0.f) ? t : 0.f;
    }
    float4* op = (float4*)(out + (size_t)d * DOUT + base);
    op[0] = make_float4(r[0], r[1], r[2], r[3]);
    op[1] = make_float4(r[4], r[5], r[6], r[7]);
}

// ---------------- launch ----------------
extern "C" void kernel_launch(void* const* d_in, const int* in_sizes, int n_in,
                              void* d_out, int out_size) {
    const float* x       = (const float*)d_in[0];
    const int*   ei      = (const int*)d_in[1];
    const float* W       = (const float*)d_in[2];
    const float* att_src = (const float*)d_in[3];
    const float* att_dst = (const float*)d_in[4];
    const float* bias    = (const float*)d_in[5];
    const float* gamma   = (const float*)d_in[6];
    const float* beta    = (const float*)d_in[7];
    float*       out     = (float*)d_out;

    zero_kernel<<<(N_NODES + 255) / 256, 256>>>();

    dim3 ggrid((N_NODES + BM - 1) / BM, DOUT / BN);
    gemm_kernel<<<ggrid, 256>>>(x, W);

    node_attn_kernel<<<6250, 256>>>(att_src, att_dst);

    scatter_kernel<<<(ET + 255) / 256, 256>>>(ei);

    aggr_kernel<<<(N_NODES * 32 + 255) / 256, 256>>>(bias, gamma, beta, out);
}

// round 5
// speedup vs baseline: 1.2846x; 1.2846x over previous
#include <cuda_runtime.h>
#include <cuda_bf16.h>
#include <math.h>
#include <stdint.h>

#define N_NODES 50000
#define N_EDGES 800000
#define ET      (N_EDGES + N_NODES)
#define DIN     256
#define HEADS   8
#define CH      32
#define DOUT    256
#define CAP     128
#define NEG_SLOPE 0.2f
#define LN_EPS  1e-5f

#define MT      391                 // ceil(50000/128)
#define MROWS   (MT * 128)          // 50048 padded rows

// ---------------- static device scratch ----------------
__device__ float g_h[(size_t)N_NODES * DOUT];
__device__ float g_asrc[N_NODES * HEADS];
__device__ float g_adst[N_NODES * HEADS];
__device__ int   g_cnt[N_NODES];
__device__ int   g_csr_src[(size_t)N_NODES * CAP];
__device__ __nv_bfloat16 g_Ahi[(size_t)MROWS * DIN];   // 25.6 MB row-major [m][k]
__device__ __nv_bfloat16 g_Alo[(size_t)MROWS * DIN];
__device__ __nv_bfloat16 g_Bhi[DOUT * DIN];            // W transposed: [n][k]
__device__ __nv_bfloat16 g_Blo[DOUT * DIN];

// ---------------- helpers ----------------
__device__ __forceinline__ uint32_t smem_u32(const void* p) {
    uint32_t a;
    asm("{ .reg .u64 t; cvta.to.shared.u64 t, %1; cvt.u32.u64 %0, t; }" : "=r"(a) : "l"(p));
    return a;
}
__device__ __forceinline__ void cp_async16(uint32_t s, const void* g) {
    asm volatile("cp.async.cg.shared.global [%0], [%1], 16;" :: "r"(s), "l"(g));
}
#define CP_COMMIT() asm volatile("cp.async.commit_group;" ::: "memory")
#define CP_WAIT0()  asm volatile("cp.async.wait_group 0;" ::: "memory")
#define CP_WAIT1()  asm volatile("cp.async.wait_group 1;" ::: "memory")

__device__ __forceinline__ void mma16816(float* d, const uint32_t* a, const uint32_t* b) {
    asm volatile(
        "mma.sync.aligned.m16n8k16.row.col.f32.bf16.bf16.f32 "
        "{%0,%1,%2,%3}, {%4,%5,%6,%7}, {%8,%9}, {%0,%1,%2,%3};"
        : "+f"(d[0]), "+f"(d[1]), "+f"(d[2]), "+f"(d[3])
        : "r"(a[0]), "r"(a[1]), "r"(a[2]), "r"(a[3]), "r"(b[0]), "r"(b[1]));
}

// ---------------- kernel 0: clear counters ----------------
__global__ void zero_kernel() {
    int t = blockIdx.x * blockDim.x + threadIdx.x;
    if (t < N_NODES) g_cnt[t] = 0;
}

// ---------------- prepass A: x -> bf16 hi/lo row-major ----------------
__global__ __launch_bounds__(256) void prepA_kernel(const float* __restrict__ x) {
    int u = blockIdx.x * blockDim.x + threadIdx.x;     // one per 8 elems
    if (u >= MROWS * (DIN / 8)) return;
    int k8  = (u & 31) * 8;
    int row = u >> 5;

    float v[8];
    if (row < N_NODES) {
        const float4* p = (const float4*)(x + (size_t)row * DIN + k8);
        float4 a = p[0], b = p[1];
        v[0]=a.x; v[1]=a.y; v[2]=a.z; v[3]=a.w; v[4]=b.x; v[5]=b.y; v[6]=b.z; v[7]=b.w;
    } else {
#pragma unroll
        for (int j = 0; j < 8; j++) v[j] = 0.f;
    }
    __nv_bfloat16 hi[8], lo[8];
#pragma unroll
    for (int j = 0; j < 8; j++) {
        hi[j] = __float2bfloat16(v[j]);
        lo[j] = __float2bfloat16(v[j] - __bfloat162float(hi[j]));
    }
    *(uint4*)(g_Ahi + (size_t)row * DIN + k8) = *(uint4*)hi;
    *(uint4*)(g_Alo + (size_t)row * DIN + k8) = *(uint4*)lo;
}

// ---------------- prepass W: W[k][n] -> Bt[n][k] bf16 hi/lo ----------------
__global__ __launch_bounds__(256) void prepW_kernel(const float* __restrict__ W) {
    int u = blockIdx.x * blockDim.x + threadIdx.x;
    if (u >= DOUT * (DIN / 8)) return;
    int k8 = (u & 31) * 8;
    int n  = u >> 5;
    __nv_bfloat16 hi[8], lo[8];
#pragma unroll
    for (int j = 0; j < 8; j++) {
        float w = W[(size_t)(k8 + j) * DOUT + n];
        hi[j] = __float2bfloat16(w);
        lo[j] = __float2bfloat16(w - __bfloat162float(hi[j]));
    }
    *(uint4*)(g_Bhi + (size_t)n * DIN + k8) = *(uint4*)hi;
    *(uint4*)(g_Blo + (size_t)n * DIN + k8) = *(uint4*)lo;
}

// ---------------- HMMA GEMM: h = x @ W, bf16 hi/lo 3-term ----------------
// smem tile: 128 rows x 32 k bf16, row stride 40 bf16 (80 B, conflict-free phases)
#define BK        32
#define ROWSTRIDE 40
#define TILE_B    (128 * ROWSTRIDE * 2)     // 10240 bytes
#define STAGE_B   (4 * TILE_B)              // Ahi, Alo, Bhi, Blo = 40960
#define SMEM_B    (2 * STAGE_B)             // 81920

__global__ __launch_bounds__(256) void gemm_mma_kernel() {
    extern __shared__ char sm[];
    uint32_t sbase = smem_u32(sm);

    int tid  = threadIdx.x;
    int wid  = tid >> 5;
    int lane = tid & 31;
    int wm   = wid >> 2;          // 0..1  (64-row slab)
    int wn   = wid & 3;           // 0..3  (32-col slab)
    int g    = lane >> 2;         // 0..7
    int t2   = (lane & 3) * 2;    // 0,2,4,6

    int m0 = blockIdx.x * 128;
    int n0 = blockIdx.y * 128;

    // per-thread global load coords: i = tid + 256*p  ->  row=i>>2, q=i&3
    const __nv_bfloat16* gsrc[4] = {
        g_Ahi + (size_t)m0 * DIN, g_Alo + (size_t)m0 * DIN,
        g_Bhi + (size_t)n0 * DIN, g_Blo + (size_t)n0 * DIN };

    float acc[4][4][4];
#pragma unroll
    for (int i = 0; i < 4; i++)
#pragma unroll
        for (int j = 0; j < 4; j++)
#pragma unroll
            for (int q = 0; q < 4; q++) acc[i][j][q] = 0.f;

    // ---- pipelined loads ----
    auto load_stage = [&](int kb, int buf) {
        uint32_t sb = sbase + buf * STAGE_B;
        int k0 = kb * BK;
#pragma unroll
        for (int tile = 0; tile < 4; tile++) {
#pragma unroll
            for (int p = 0; p < 2; p++) {
                int i   = tid + p * 256;
                int row = i >> 2, q = i & 3;
                uint32_t soff = sb + tile * TILE_B + (row * ROWSTRIDE + q * 8) * 2;
                cp_async16(soff, gsrc[tile] + (size_t)row * DIN + k0 + q * 8);
            }
        }
        CP_COMMIT();
    };

    load_stage(0, 0);

    for (int kb = 0; kb < 8; kb++) {
        int buf = kb & 1;
        if (kb < 7) load_stage(kb + 1, buf ^ 1);
        if (kb < 7) CP_WAIT1(); else CP_WAIT0();
        __syncthreads();

        const __nv_bfloat16* sAhi = (const __nv_bfloat16*)(sm + buf * STAGE_B);
        const __nv_bfloat16* sAlo = sAhi + 128 * ROWSTRIDE;
        const __nv_bfloat16* sBhi = sAlo + 128 * ROWSTRIDE;
        const __nv_bfloat16* sBlo = sBhi + 128 * ROWSTRIDE;

#pragma unroll
        for (int ks = 0; ks < 2; ks++) {
            int kk = ks * 16 + t2;
            uint32_t bf[4][2][2];
#pragma unroll
            for (int j = 0; j < 4; j++) {
                int nr = wn * 32 + j * 8 + g;
                bf[j][0][0] = *(const uint32_t*)(sBhi + nr * ROWSTRIDE + kk);
                bf[j][0][1] = *(const uint32_t*)(sBhi + nr * ROWSTRIDE + kk + 8);
                bf[j][1][0] = *(const uint32_t*)(sBlo + nr * ROWSTRIDE + kk);
                bf[j][1][1] = *(const uint32_t*)(sBlo + nr * ROWSTRIDE + kk + 8);
            }
#pragma unroll
            for (int i = 0; i < 4; i++) {
                int mr = wm * 64 + i * 16 + g;
                uint32_t ah[4], al[4];
                ah[0] = *(const uint32_t*)(sAhi + mr * ROWSTRIDE + kk);
                ah[1] = *(const uint32_t*)(sAhi + (mr + 8) * ROWSTRIDE + kk);
                ah[2] = *(const uint32_t*)(sAhi + mr * ROWSTRIDE + kk + 8);
                ah[3] = *(const uint32_t*)(sAhi + (mr + 8) * ROWSTRIDE + kk + 8);
                al[0] = *(const uint32_t*)(sAlo + mr * ROWSTRIDE + kk);
                al[1] = *(const uint32_t*)(sAlo + (mr + 8) * ROWSTRIDE + kk);
                al[2] = *(const uint32_t*)(sAlo + mr * ROWSTRIDE + kk + 8);
                al[3] = *(const uint32_t*)(sAlo + (mr + 8) * ROWSTRIDE + kk + 8);
#pragma unroll
                for (int j = 0; j < 4; j++) {
                    mma16816(acc[i][j], ah, bf[j][0]);   // hi @ W_hi
                    mma16816(acc[i][j], ah, bf[j][1]);   // hi @ W_lo
                    mma16816(acc[i][j], al, bf[j][0]);   // lo @ W_hi
                }
            }
        }
        __syncthreads();
    }

    // ---- epilogue: per PTX ISA C fragment layout ----
#pragma unroll
    for (int i = 0; i < 4; i++) {
        int m = m0 + wm * 64 + i * 16 + g;
#pragma unroll
        for (int j = 0; j < 4; j++) {
            int col = n0 + wn * 32 + j * 8 + t2;
            if (m < N_NODES)
                *(float2*)(g_h + (size_t)m * DOUT + col) = make_float2(acc[i][j][0], acc[i][j][1]);
            if (m + 8 < N_NODES)
                *(float2*)(g_h + (size_t)(m + 8) * DOUT + col) = make_float2(acc[i][j][2], acc[i][j][3]);
        }
    }
}

// ---------------- per-node attention dots ----------------
__global__ void node_attn_kernel(const float* __restrict__ att_src,
                                 const float* __restrict__ att_dst) {
    int warp  = (blockIdx.x * blockDim.x + threadIdx.x) >> 5;
    int lane  = threadIdx.x & 31;
    int nwarp = (gridDim.x * blockDim.x) >> 5;
    for (int n = warp; n < N_NODES; n += nwarp) {
        const float* hr = g_h + (size_t)n * DOUT;
#pragma unroll
        for (int j = 0; j < HEADS; j++) {
            float v  = hr[j * CH + lane];
            float ps = v * att_src[j * CH + lane];
            float pd = v * att_dst[j * CH + lane];
#pragma unroll
            for (int o = 16; o > 0; o >>= 1) {
                ps += __shfl_xor_sync(0xFFFFFFFFu, ps, o);
                pd += __shfl_xor_sync(0xFFFFFFFFu, pd, o);
            }
            if (lane == 0) {
                g_asrc[n * HEADS + j] = ps;
                g_adst[n * HEADS + j] = pd;
            }
        }
    }
}

// ---------------- bucket edges by dst ----------------
__global__ void scatter_kernel(const int* __restrict__ ei) {
    int t = blockIdx.x * blockDim.x + threadIdx.x;
    if (t >= ET) return;
    int s, d;
    if (t < N_EDGES) {
        s = ei[t];
        d = ei[N_EDGES + t];
    } else {
        s = d = t - N_EDGES;
    }
    if ((unsigned)s >= N_NODES || (unsigned)d >= N_NODES) return;
    int pos = atomicAdd(&g_cnt[d], 1);
    if (pos < CAP) g_csr_src[(size_t)d * CAP + pos] = s;
}

// ---------------- warp-per-dst softmax-aggregate + bias + LN + ReLU ----------------
__global__ __launch_bounds__(256) void aggr_kernel(const float* __restrict__ bias,
                                                   const float* __restrict__ gamma,
                                                   const float* __restrict__ beta,
                                                   float* __restrict__ out) {
    int warp = (blockIdx.x * blockDim.x + threadIdx.x) >> 5;
    int lane = threadIdx.x & 31;
    if (warp >= N_NODES) return;
    int d    = warp;
    int head = lane >> 2;
    int base = lane * 8;

    float adv = g_adst[d * HEADS + head];
    int cnt = g_cnt[d];
    if (cnt > CAP) cnt = CAP;

    float4 acc0 = make_float4(0.f, 0.f, 0.f, 0.f);
    float4 acc1 = make_float4(0.f, 0.f, 0.f, 0.f);
    float  S = 0.f;

    const int* lst = g_csr_src + (size_t)d * CAP;
    int s = (cnt > 0) ? lst[0] : 0;
    for (int i = 0; i < cnt; i++) {
        int s_nxt = (i + 1 < cnt) ? lst[i + 1] : 0;
        float e = g_asrc[s * HEADS + head] + adv;
        e = (e > 0.f) ? e : NEG_SLOPE * e;
        float ex = __expf(e);
        S += ex;
        const float4* hp = (const float4*)(g_h + (size_t)s * DOUT + base);
        float4 h0 = hp[0], h1 = hp[1];
        acc0.x += ex * h0.x; acc0.y += ex * h0.y; acc0.z += ex * h0.z; acc0.w += ex * h0.w;
        acc1.x += ex * h1.x; acc1.y += ex * h1.y; acc1.z += ex * h1.z; acc1.w += ex * h1.w;
        s = s_nxt;
    }
    float inv = 1.f / S;

    float v[8];
    v[0] = acc0.x * inv + bias[base + 0];
    v[1] = acc0.y * inv + bias[base + 1];
    v[2] = acc0.z * inv + bias[base + 2];
    v[3] = acc0.w * inv + bias[base + 3];
    v[4] = acc1.x * inv + bias[base + 4];
    v[5] = acc1.y * inv + bias[base + 5];
    v[6] = acc1.z * inv + bias[base + 6];
    v[7] = acc1.w * inv + bias[base + 7];

    float sum = 0.f, sq = 0.f;
#pragma unroll
    for (int k = 0; k < 8; k++) { sum += v[k]; sq += v[k] * v[k]; }
#pragma unroll
    for (int o = 16; o > 0; o >>= 1) {
        sum += __shfl_xor_sync(0xFFFFFFFFu, sum, o);
        sq  += __shfl_xor_sync(0xFFFFFFFFu, sq,  o);
    }
    float mu   = sum * (1.f / 256.f);
    float var  = sq * (1.f / 256.f) - mu * mu;
    float rstd = rsqrtf(var + LN_EPS);

    float r[8];
#pragma unroll
    for (int k = 0; k < 8; k++) {
        float tt = (v[k] - mu) * rstd * gamma[base + k] + beta[base + k];
        r[k] = (tt > 0.f) ? tt : 0.f;
    }
    float4* op = (float4*)(out + (size_t)d * DOUT + base);
    op[0] = make_float4(r[0], r[1], r[2], r[3]);
    op[1] = make_float4(r[4], r[5], r[6], r[7]);
}

// ---------------- launch ----------------
extern "C" void kernel_launch(void* const* d_in, const int* in_sizes, int n_in,
                              void* d_out, int out_size) {
    const float* x       = (const float*)d_in[0];
    const int*   ei      = (const int*)d_in[1];
    const float* W       = (const float*)d_in[2];
    const float* att_src = (const float*)d_in[3];
    const float* att_dst = (const float*)d_in[4];
    const float* bias    = (const float*)d_in[5];
    const float* gamma   = (const float*)d_in[6];
    const float* beta    = (const float*)d_in[7];
    float*       out     = (float*)d_out;

    static bool attr_set = false;
    if (!attr_set) {
        cudaFuncSetAttribute(gemm_mma_kernel, cudaFuncAttributeMaxDynamicSharedMemorySize, SMEM_B);
        attr_set = true;
    }

    zero_kernel<<<(N_NODES + 255) / 256, 256>>>();

    prepA_kernel<<<(MROWS * 32 + 255) / 256, 256>>>(x);
    prepW_kernel<<<(DOUT * 32 + 255) / 256, 256>>>(W);

    dim3 ggrid(MT, 2);
    gemm_mma_kernel<<<ggrid, 256, SMEM_B>>>();

    node_attn_kernel<<<6250, 256>>>(att_src, att_dst);

    scatter_kernel<<<(ET + 255) / 256, 256>>>(ei);

    aggr_kernel<<<(N_NODES * 32 + 255) / 256, 256>>>(bias, gamma, beta, out);
}

// round 6
// speedup vs baseline: 1.3962x; 1.0868x over previous
#include <cuda_runtime.h>
#include <cuda_bf16.h>
#include <cuda_fp16.h>
#include <math.h>
#include <stdint.h>

#define N_NODES 50000
#define N_EDGES 800000
#define ET      (N_EDGES + N_NODES)
#define DIN     256
#define HEADS   8
#define CH      32
#define DOUT    256
#define CAP     128
#define NEG_SLOPE 0.2f
#define LN_EPS  1e-5f

#define MT      391                 // ceil(50000/128)
#define MROWS   (MT * 128)          // 50048 padded rows

// ---------------- static device scratch ----------------
__device__ float g_h[(size_t)N_NODES * DOUT];          // fp32 h (attn dots)
__device__ __half g_hf[(size_t)N_NODES * DOUT];        // fp16 h (message gathers)
__device__ float g_asrc[N_NODES * HEADS];
__device__ float g_adst[N_NODES * HEADS];
__device__ int   g_cnt[N_NODES];
__device__ int   g_csr_src[(size_t)N_NODES * CAP];
__device__ __nv_bfloat16 g_Ahi[(size_t)MROWS * DIN];   // 25.6 MB row-major [m][k]
__device__ __nv_bfloat16 g_Alo[(size_t)MROWS * DIN];
__device__ __nv_bfloat16 g_Bhi[DOUT * DIN];            // W transposed: [n][k]
__device__ __nv_bfloat16 g_Blo[DOUT * DIN];

// ---------------- helpers ----------------
__device__ __forceinline__ uint32_t smem_u32(const void* p) {
    uint32_t a;
    asm("{ .reg .u64 t; cvta.to.shared.u64 t, %1; cvt.u32.u64 %0, t; }" : "=r"(a) : "l"(p));
    return a;
}
__device__ __forceinline__ void cp_async16(uint32_t s, const void* g) {
    asm volatile("cp.async.cg.shared.global [%0], [%1], 16;" :: "r"(s), "l"(g));
}
#define CP_COMMIT() asm volatile("cp.async.commit_group;" ::: "memory")
#define CP_WAIT0()  asm volatile("cp.async.wait_group 0;" ::: "memory")
#define CP_WAIT1()  asm volatile("cp.async.wait_group 1;" ::: "memory")

__device__ __forceinline__ void mma16816(float* d, const uint32_t* a, const uint32_t* b) {
    asm volatile(
        "mma.sync.aligned.m16n8k16.row.col.f32.bf16.bf16.f32 "
        "{%0,%1,%2,%3}, {%4,%5,%6,%7}, {%8,%9}, {%0,%1,%2,%3};"
        : "+f"(d[0]), "+f"(d[1]), "+f"(d[2]), "+f"(d[3])
        : "r"(a[0]), "r"(a[1]), "r"(a[2]), "r"(a[3]), "r"(b[0]), "r"(b[1]));
}

// ---------------- kernel 0: clear counters ----------------
__global__ void zero_kernel() {
    int t = blockIdx.x * blockDim.x + threadIdx.x;
    if (t < N_NODES) g_cnt[t] = 0;
}

// ---------------- prepass A: x -> bf16 hi/lo row-major ----------------
__global__ __launch_bounds__(256) void prepA_kernel(const float* __restrict__ x) {
    int u = blockIdx.x * blockDim.x + threadIdx.x;     // one per 8 elems
    if (u >= MROWS * (DIN / 8)) return;
    int k8  = (u & 31) * 8;
    int row = u >> 5;

    float v[8];
    if (row < N_NODES) {
        const float4* p = (const float4*)(x + (size_t)row * DIN + k8);
        float4 a = p[0], b = p[1];
        v[0]=a.x; v[1]=a.y; v[2]=a.z; v[3]=a.w; v[4]=b.x; v[5]=b.y; v[6]=b.z; v[7]=b.w;
    } else {
#pragma unroll
        for (int j = 0; j < 8; j++) v[j] = 0.f;
    }
    __nv_bfloat16 hi[8], lo[8];
#pragma unroll
    for (int j = 0; j < 8; j++) {
        hi[j] = __float2bfloat16(v[j]);
        lo[j] = __float2bfloat16(v[j] - __bfloat162float(hi[j]));
    }
    *(uint4*)(g_Ahi + (size_t)row * DIN + k8) = *(uint4*)hi;
    *(uint4*)(g_Alo + (size_t)row * DIN + k8) = *(uint4*)lo;
}

// ---------------- prepass W: W[k][n] -> Bt[n][k] bf16 hi/lo ----------------
__global__ __launch_bounds__(256) void prepW_kernel(const float* __restrict__ W) {
    int u = blockIdx.x * blockDim.x + threadIdx.x;
    if (u >= DOUT * (DIN / 8)) return;
    int k8 = (u & 31) * 8;
    int n  = u >> 5;
    __nv_bfloat16 hi[8], lo[8];
#pragma unroll
    for (int j = 0; j < 8; j++) {
        float w = W[(size_t)(k8 + j) * DOUT + n];
        hi[j] = __float2bfloat16(w);
        lo[j] = __float2bfloat16(w - __bfloat162float(hi[j]));
    }
    *(uint4*)(g_Bhi + (size_t)n * DIN + k8) = *(uint4*)hi;
    *(uint4*)(g_Blo + (size_t)n * DIN + k8) = *(uint4*)lo;
}

// ---------------- HMMA GEMM: h = x @ W, bf16 hi/lo 3-term ----------------
#define BK        32
#define ROWSTRIDE 40
#define TILE_B    (128 * ROWSTRIDE * 2)     // 10240 bytes
#define STAGE_B   (4 * TILE_B)              // 40960
#define SMEM_B    (2 * STAGE_B)             // 81920

__global__ __launch_bounds__(256) void gemm_mma_kernel() {
    extern __shared__ char sm[];
    uint32_t sbase = smem_u32(sm);

    int tid  = threadIdx.x;
    int wid  = tid >> 5;
    int lane = tid & 31;
    int wm   = wid >> 2;          // 0..1
    int wn   = wid & 3;           // 0..3
    int g    = lane >> 2;         // 0..7
    int t2   = (lane & 3) * 2;    // 0,2,4,6

    int m0 = blockIdx.x * 128;
    int n0 = blockIdx.y * 128;

    const __nv_bfloat16* gsrc[4] = {
        g_Ahi + (size_t)m0 * DIN, g_Alo + (size_t)m0 * DIN,
        g_Bhi + (size_t)n0 * DIN, g_Blo + (size_t)n0 * DIN };

    float acc[4][4][4];
#pragma unroll
    for (int i = 0; i < 4; i++)
#pragma unroll
        for (int j = 0; j < 4; j++)
#pragma unroll
            for (int q = 0; q < 4; q++) acc[i][j][q] = 0.f;

    auto load_stage = [&](int kb, int buf) {
        uint32_t sb = sbase + buf * STAGE_B;
        int k0 = kb * BK;
#pragma unroll
        for (int tile = 0; tile < 4; tile++) {
#pragma unroll
            for (int p = 0; p < 2; p++) {
                int i   = tid + p * 256;
                int row = i >> 2, q = i & 3;
                uint32_t soff = sb + tile * TILE_B + (row * ROWSTRIDE + q * 8) * 2;
                cp_async16(soff, gsrc[tile] + (size_t)row * DIN + k0 + q * 8);
            }
        }
        CP_COMMIT();
    };

    load_stage(0, 0);

    for (int kb = 0; kb < 8; kb++) {
        int buf = kb & 1;
        if (kb < 7) load_stage(kb + 1, buf ^ 1);
        if (kb < 7) CP_WAIT1(); else CP_WAIT0();
        __syncthreads();

        const __nv_bfloat16* sAhi = (const __nv_bfloat16*)(sm + buf * STAGE_B);
        const __nv_bfloat16* sAlo = sAhi + 128 * ROWSTRIDE;
        const __nv_bfloat16* sBhi = sAlo + 128 * ROWSTRIDE;
        const __nv_bfloat16* sBlo = sBhi + 128 * ROWSTRIDE;

#pragma unroll
        for (int ks = 0; ks < 2; ks++) {
            int kk = ks * 16 + t2;
            uint32_t bf[4][2][2];
#pragma unroll
            for (int j = 0; j < 4; j++) {
                int nr = wn * 32 + j * 8 + g;
                bf[j][0][0] = *(const uint32_t*)(sBhi + nr * ROWSTRIDE + kk);
                bf[j][0][1] = *(const uint32_t*)(sBhi + nr * ROWSTRIDE + kk + 8);
                bf[j][1][0] = *(const uint32_t*)(sBlo + nr * ROWSTRIDE + kk);
                bf[j][1][1] = *(const uint32_t*)(sBlo + nr * ROWSTRIDE + kk + 8);
            }
#pragma unroll
            for (int i = 0; i < 4; i++) {
                int mr = wm * 64 + i * 16 + g;
                uint32_t ah[4], al[4];
                ah[0] = *(const uint32_t*)(sAhi + mr * ROWSTRIDE + kk);
                ah[1] = *(const uint32_t*)(sAhi + (mr + 8) * ROWSTRIDE + kk);
                ah[2] = *(const uint32_t*)(sAhi + mr * ROWSTRIDE + kk + 8);
                ah[3] = *(const uint32_t*)(sAhi + (mr + 8) * ROWSTRIDE + kk + 8);
                al[0] = *(const uint32_t*)(sAlo + mr * ROWSTRIDE + kk);
                al[1] = *(const uint32_t*)(sAlo + (mr + 8) * ROWSTRIDE + kk);
                al[2] = *(const uint32_t*)(sAlo + mr * ROWSTRIDE + kk + 8);
                al[3] = *(const uint32_t*)(sAlo + (mr + 8) * ROWSTRIDE + kk + 8);
#pragma unroll
                for (int j = 0; j < 4; j++) {
                    mma16816(acc[i][j], ah, bf[j][0]);   // hi @ W_hi
                    mma16816(acc[i][j], ah, bf[j][1]);   // hi @ W_lo
                    mma16816(acc[i][j], al, bf[j][0]);   // lo @ W_hi
                }
            }
        }
        __syncthreads();
    }

    // ---- epilogue: write fp32 h + fp16 copy ----
#pragma unroll
    for (int i = 0; i < 4; i++) {
        int m = m0 + wm * 64 + i * 16 + g;
#pragma unroll
        for (int j = 0; j < 4; j++) {
            int col = n0 + wn * 32 + j * 8 + t2;
            if (m < N_NODES) {
                *(float2*)(g_h + (size_t)m * DOUT + col) = make_float2(acc[i][j][0], acc[i][j][1]);
                *(__half2*)(g_hf + (size_t)m * DOUT + col) =
                    __floats2half2_rn(acc[i][j][0], acc[i][j][1]);
            }
            if (m + 8 < N_NODES) {
                *(float2*)(g_h + (size_t)(m + 8) * DOUT + col) = make_float2(acc[i][j][2], acc[i][j][3]);
                *(__half2*)(g_hf + (size_t)(m + 8) * DOUT + col) =
                    __floats2half2_rn(acc[i][j][2], acc[i][j][3]);
            }
        }
    }
}

// ---------------- per-node attention dots (fp32 h) ----------------
__global__ void node_attn_kernel(const float* __restrict__ att_src,
                                 const float* __restrict__ att_dst) {
    int warp  = (blockIdx.x * blockDim.x + threadIdx.x) >> 5;
    int lane  = threadIdx.x & 31;
    int nwarp = (gridDim.x * blockDim.x) >> 5;
    for (int n = warp; n < N_NODES; n += nwarp) {
        const float* hr = g_h + (size_t)n * DOUT;
#pragma unroll
        for (int j = 0; j < HEADS; j++) {
            float v  = hr[j * CH + lane];
            float ps = v * att_src[j * CH + lane];
            float pd = v * att_dst[j * CH + lane];
#pragma unroll
            for (int o = 16; o > 0; o >>= 1) {
                ps += __shfl_xor_sync(0xFFFFFFFFu, ps, o);
                pd += __shfl_xor_sync(0xFFFFFFFFu, pd, o);
            }
            if (lane == 0) {
                g_asrc[n * HEADS + j] = ps;
                g_adst[n * HEADS + j] = pd;
            }
        }
    }
}

// ---------------- bucket edges by dst ----------------
__global__ void scatter_kernel(const int* __restrict__ ei) {
    int t = blockIdx.x * blockDim.x + threadIdx.x;
    if (t >= ET) return;
    int s, d;
    if (t < N_EDGES) {
        s = ei[t];
        d = ei[N_EDGES + t];
    } else {
        s = d = t - N_EDGES;
    }
    if ((unsigned)s >= N_NODES || (unsigned)d >= N_NODES) return;
    int pos = atomicAdd(&g_cnt[d], 1);
    if (pos < CAP) g_csr_src[(size_t)d * CAP + pos] = s;
}

// ---------------- warp-per-dst softmax-aggregate (fp16 gathers) + bias + LN + ReLU ----------------
__global__ __launch_bounds__(256) void aggr_kernel(const float* __restrict__ bias,
                                                   const float* __restrict__ gamma,
                                                   const float* __restrict__ beta,
                                                   float* __restrict__ out) {
    int warp = (blockIdx.x * blockDim.x + threadIdx.x) >> 5;
    int lane = threadIdx.x & 31;
    if (warp >= N_NODES) return;
    int d    = warp;
    int head = lane >> 2;
    int base = lane * 8;

    float adv = g_adst[d * HEADS + head];
    int cnt = g_cnt[d];
    if (cnt > CAP) cnt = CAP;

    float acc[8];
#pragma unroll
    for (int q = 0; q < 8; q++) acc[q] = 0.f;
    float S = 0.f;

    const int* lst = g_csr_src + (size_t)d * CAP;
    int s = (cnt > 0) ? lst[0] : 0;
    for (int i = 0; i < cnt; i++) {
        int s_nxt = (i + 1 < cnt) ? lst[i + 1] : 0;
        float e = g_asrc[s * HEADS + head] + adv;
        e = (e > 0.f) ? e : NEG_SLOPE * e;
        float ex = __expf(e);
        S += ex;
        uint4 hv = *(const uint4*)(g_hf + (size_t)s * DOUT + base);   // 8 halfs
        float2 f0 = __half22float2(*(__half2*)&hv.x);
        float2 f1 = __half22float2(*(__half2*)&hv.y);
        float2 f2 = __half22float2(*(__half2*)&hv.z);
        float2 f3 = __half22float2(*(__half2*)&hv.w);
        acc[0] += ex * f0.x; acc[1] += ex * f0.y;
        acc[2] += ex * f1.x; acc[3] += ex * f1.y;
        acc[4] += ex * f2.x; acc[5] += ex * f2.y;
        acc[6] += ex * f3.x; acc[7] += ex * f3.y;
        s = s_nxt;
    }
    float inv = 1.f / S;

    float v[8];
#pragma unroll
    for (int q = 0; q < 8; q++) v[q] = acc[q] * inv + bias[base + q];

    float sum = 0.f, sq = 0.f;
#pragma unroll
    for (int k = 0; k < 8; k++) { sum += v[k]; sq += v[k] * v[k]; }
#pragma unroll
    for (int o = 16; o > 0; o >>= 1) {
        sum += __shfl_xor_sync(0xFFFFFFFFu, sum, o);
        sq  += __shfl_xor_sync(0xFFFFFFFFu, sq,  o);
    }
    float mu   = sum * (1.f / 256.f);
    float var  = sq * (1.f / 256.f) - mu * mu;
    float rstd = rsqrtf(var + LN_EPS);

    float r[8];
#pragma unroll
    for (int k = 0; k < 8; k++) {
        float tt = (v[k] - mu) * rstd * gamma[base + k] + beta[base + k];
        r[k] = (tt > 0.f) ? tt : 0.f;
    }
    float4* op = (float4*)(out + (size_t)d * DOUT + base);
    op[0] = make_float4(r[0], r[1], r[2], r[3]);
    op[1] = make_float4(r[4], r[5], r[6], r[7]);
}

// ---------------- launch ----------------
extern "C" void kernel_launch(void* const* d_in, const int* in_sizes, int n_in,
                              void* d_out, int out_size) {
    const float* x       = (const float*)d_in[0];
    const int*   ei      = (const int*)d_in[1];
    const float* W       = (const float*)d_in[2];
    const float* att_src = (const float*)d_in[3];
    const float* att_dst = (const float*)d_in[4];
    const float* bias    = (const float*)d_in[5];
    const float* gamma   = (const float*)d_in[6];
    const float* beta    = (const float*)d_in[7];
    float*       out     = (float*)d_out;

    static bool attr_set = false;
    if (!attr_set) {
        cudaFuncSetAttribute(gemm_mma_kernel, cudaFuncAttributeMaxDynamicSharedMemorySize, SMEM_B);
        attr_set = true;
    }

    zero_kernel<<<(N_NODES + 255) / 256, 256>>>();

    prepA_kernel<<<(MROWS * 32 + 255) / 256, 256>>>(x);
    prepW_kernel<<<(DOUT * 32 + 255) / 256, 256>>>(W);

    dim3 ggrid(MT, 2);
    gemm_mma_kernel<<<ggrid, 256, SMEM_B>>>();

    node_attn_kernel<<<6250, 256>>>(att_src, att_dst);

    scatter_kernel<<<(ET + 255) / 256, 256>>>(ei);

    aggr_kernel<<<(N_NODES * 32 + 255) / 256, 256>>>(bias, gamma, beta, out);
}